// round 2
// baseline (speedup 1.0000x reference)
#include <cuda_runtime.h>
#include <cuda_bf16.h>
#include <cstdint>

// Problem constants
#define HID   256
#define HID2  512
#define MAXN  50000

// Scratch: per-node projections AB[n,0:256]=z@W1_top, AB[n,256:512]=z@W1_bot
__device__ float g_AB[(size_t)MAXN * HID2];
// Packed weight Wc[k, j]: j<256 -> W1[k, j]; j>=256 -> W1[256+k, j-256]
__device__ float g_Wc[HID * HID2];
// 1 if edge_index is stored as int64 on device, 0 if int32
__device__ int g_idx64_flag;

// ---------------------------------------------------------------------------
// Kernel P: probe edge_index dtype. int32 data viewed as int64 packs two
// random indices into a + b*2^32 which lands far outside [0, N).
// ---------------------------------------------------------------------------
__global__ void probe_kernel(const void* __restrict__ ei, int E, int N) {
    __shared__ int ok;
    if (threadIdx.x == 0) ok = 1;
    __syncthreads();
    const long long* p = (const long long*)ei;
    int total = 2 * E;
    int samples = total < 4096 ? total : 4096;
    for (int i = threadIdx.x; i < samples; i += blockDim.x) {
        long long v = p[i];
        if (v < 0 || v >= (long long)N) ok = 0;
    }
    __syncthreads();
    if (threadIdx.x == 0) g_idx64_flag = ok;
}

// ---------------------------------------------------------------------------
// Kernel 0: pack W1 [512,256] into Wc [256,512]
// ---------------------------------------------------------------------------
__global__ void pack_w_kernel(const float* __restrict__ W1) {
    int idx = blockIdx.x * blockDim.x + threadIdx.x;
    if (idx >= HID * HID2) return;
    int k = idx >> 9;          // 0..255
    int j = idx & (HID2 - 1);  // 0..511
    float v = (j < HID) ? W1[k * HID + j]
                        : W1[(HID + k) * HID + (j - HID)];
    g_Wc[idx] = v;
}

// ---------------------------------------------------------------------------
// Kernel 1: SGEMM  g_AB[M,512] = z[M,256] @ g_Wc[256,512]
// 128x128 block tile, BK=8, 8x8 per thread, 256 threads.
// ---------------------------------------------------------------------------
#define BM 128
#define BN 128
#define BK 8
#define TM 8
#define TN 8

__global__ __launch_bounds__(256, 2)
void sgemm_kernel(const float* __restrict__ A, int M) {
    const int K = HID, N = HID2;
    __shared__ float As[BK][BM];
    __shared__ float Bs[BK][BN];

    int tid = threadIdx.x;
    int blockRow = blockIdx.y * BM;
    int blockCol = blockIdx.x * BN;

    int aRow = tid >> 1;            // 0..127
    int aCol = (tid & 1) * 4;       // 0 or 4
    int bRow = tid >> 5;            // 0..7
    int bCol = (tid & 31) * 4;      // 0..124

    int tRow = (tid >> 4) * TM;     // 0..120
    int tCol = (tid & 15) * TN;     // 0..120

    float acc[TM][TN];
#pragma unroll
    for (int i = 0; i < TM; i++)
#pragma unroll
        for (int j = 0; j < TN; j++) acc[i][j] = 0.f;

    for (int k0 = 0; k0 < K; k0 += BK) {
        int gRow = blockRow + aRow;
        float4 av = make_float4(0.f, 0.f, 0.f, 0.f);
        if (gRow < M)
            av = *reinterpret_cast<const float4*>(A + (size_t)gRow * K + k0 + aCol);
        As[aCol + 0][aRow] = av.x;
        As[aCol + 1][aRow] = av.y;
        As[aCol + 2][aRow] = av.z;
        As[aCol + 3][aRow] = av.w;

        float4 bv = *reinterpret_cast<const float4*>(
            g_Wc + (size_t)(k0 + bRow) * N + blockCol + bCol);
        *reinterpret_cast<float4*>(&Bs[bRow][bCol]) = bv;

        __syncthreads();

        float regM[TM], regN[TN];
#pragma unroll
        for (int k = 0; k < BK; k++) {
#pragma unroll
            for (int i = 0; i < TM; i += 4) {
                float4 v = *reinterpret_cast<const float4*>(&As[k][tRow + i]);
                regM[i + 0] = v.x; regM[i + 1] = v.y;
                regM[i + 2] = v.z; regM[i + 3] = v.w;
            }
#pragma unroll
            for (int j = 0; j < TN; j += 4) {
                float4 v = *reinterpret_cast<const float4*>(&Bs[k][tCol + j]);
                regN[j + 0] = v.x; regN[j + 1] = v.y;
                regN[j + 2] = v.z; regN[j + 3] = v.w;
            }
#pragma unroll
            for (int i = 0; i < TM; i++)
#pragma unroll
                for (int j = 0; j < TN; j++)
                    acc[i][j] = fmaf(regM[i], regN[j], acc[i][j]);
        }
        __syncthreads();
    }

#pragma unroll
    for (int i = 0; i < TM; i++) {
        int gRow = blockRow + tRow + i;
        if (gRow < M) {
#pragma unroll
            for (int j = 0; j < TN; j += 4) {
                float4 v = make_float4(acc[i][j], acc[i][j + 1],
                                       acc[i][j + 2], acc[i][j + 3]);
                *reinterpret_cast<float4*>(
                    g_AB + (size_t)gRow * HID2 + blockCol + tCol + j) = v;
            }
        }
    }
}

// ---------------------------------------------------------------------------
// Kernel 2: per-edge score. One warp per edge.
// score[e] = sum_h relu(AB[src,h] + AB[dst,256+h] + b1[h]) * W2[h] + b2
// ---------------------------------------------------------------------------
__global__ __launch_bounds__(256)
void edge_kernel(const void* __restrict__ ei_raw,
                 const float* __restrict__ b1,
                 const float* __restrict__ W2,
                 const float* __restrict__ b2,
                 float* __restrict__ out,
                 int E, int M) {
    int gtid = blockIdx.x * blockDim.x + threadIdx.x;
    int warp = gtid >> 5;
    int lane = gtid & 31;
    if (warp >= E) return;

    long long s, d;
    if (g_idx64_flag) {
        const long long* ei = (const long long*)ei_raw;
        s = ei[warp];
        d = ei[(size_t)E + warp];
    } else {
        const int* ei = (const int*)ei_raw;
        s = ei[warp];
        d = ei[(size_t)E + warp];
    }
    // Clamp guard (no-op when interpretation is correct)
    s = s < 0 ? 0 : (s >= M ? M - 1 : s);
    d = d < 0 ? 0 : (d >= M ? M - 1 : d);

    const float4* __restrict__ Arow =
        reinterpret_cast<const float4*>(g_AB + (size_t)s * HID2);
    const float4* __restrict__ Brow =
        reinterpret_cast<const float4*>(g_AB + (size_t)d * HID2 + HID);
    const float4* __restrict__ b1v = reinterpret_cast<const float4*>(b1);
    const float4* __restrict__ w2v = reinterpret_cast<const float4*>(W2);

    float acc = 0.f;
#pragma unroll
    for (int i = 0; i < 2; i++) {
        int h4 = lane + i * 32;   // float4 index in [0,64)
        float4 a  = __ldg(&Arow[h4]);
        float4 b  = __ldg(&Brow[h4]);
        float4 bb = __ldg(&b1v[h4]);
        float4 w  = __ldg(&w2v[h4]);
        acc = fmaf(fmaxf(a.x + b.x + bb.x, 0.f), w.x, acc);
        acc = fmaf(fmaxf(a.y + b.y + bb.y, 0.f), w.y, acc);
        acc = fmaf(fmaxf(a.z + b.z + bb.z, 0.f), w.z, acc);
        acc = fmaf(fmaxf(a.w + b.w + bb.w, 0.f), w.w, acc);
    }
#pragma unroll
    for (int off = 16; off > 0; off >>= 1)
        acc += __shfl_xor_sync(0xFFFFFFFFu, acc, off);

    if (lane == 0)
        out[warp] = acc + __ldg(b2);
}

// ---------------------------------------------------------------------------
// Launch
// Inputs: 0:z [N*256] f32, 1:edge_index [2*E] (int64 or int32), 2:W1 [512*256],
//         3:b1 [256], 4:W2 [256], 5:b2 [1]
// ---------------------------------------------------------------------------
extern "C" void kernel_launch(void* const* d_in, const int* in_sizes, int n_in,
                              void* d_out, int out_size) {
    const float* z  = (const float*)d_in[0];
    const void*  ei = d_in[1];
    const float* W1 = (const float*)d_in[2];
    const float* b1 = (const float*)d_in[3];
    const float* W2 = (const float*)d_in[4];
    const float* b2 = (const float*)d_in[5];
    float* out = (float*)d_out;

    int M = in_sizes[0] / HID;   // nodes (50000)
    int E = in_sizes[1] / 2;     // edges (800000)

    probe_kernel<<<1, 256>>>(ei, E, M);
    pack_w_kernel<<<(HID * HID2 + 255) / 256, 256>>>(W1);

    dim3 grid1(HID2 / BN, (M + BM - 1) / BM);
    sgemm_kernel<<<grid1, 256>>>(z, M);

    int blocks = (E * 32 + 255) / 256;
    edge_kernel<<<blocks, 256>>>(ei, b1, W2, b2, out, E, M);
}

// round 3
// speedup vs baseline: 1.1426x; 1.1426x over previous
#include <cuda_runtime.h>
#include <cuda_bf16.h>
#include <cstdint>

#define HID   256
#define HID2  512
#define MAXN  50000

// Scratch: AB[n,0:256]=z@W1_top, AB[n,256:512]=z@W1_bot + b1
__device__ float g_AB[(size_t)MAXN * HID2];
// Packed weight Wc[k, j]: j<256 -> W1[k, j]; j>=256 -> W1[256+k, j-256]
__device__ float g_Wc[HID * HID2];
__device__ int g_idx64_flag;

// ---------------------------------------------------------------------------
// f32x2 packed-FMA helpers (Blackwell; ptxas never emits FFMA2 from C++)
// ---------------------------------------------------------------------------
__device__ __forceinline__ unsigned long long fdup2(float x) {
    unsigned long long r;
    asm("mov.b64 %0, {%1, %1};" : "=l"(r) : "f"(x));
    return r;
}
__device__ __forceinline__ unsigned long long ffma2(unsigned long long a,
                                                    unsigned long long b,
                                                    unsigned long long c) {
    unsigned long long d;
    asm("fma.rn.f32x2 %0, %1, %2, %3;" : "=l"(d) : "l"(a), "l"(b), "l"(c));
    return d;
}
__device__ __forceinline__ void funpack2(unsigned long long v, float& lo, float& hi) {
    asm("mov.b64 {%0, %1}, %2;" : "=f"(lo), "=f"(hi) : "l"(v));
}

// ---------------------------------------------------------------------------
// Probe edge_index dtype (int64 vs int32 on device)
// ---------------------------------------------------------------------------
__global__ void probe_kernel(const void* __restrict__ ei, int E, int N) {
    __shared__ int ok;
    if (threadIdx.x == 0) ok = 1;
    __syncthreads();
    const long long* p = (const long long*)ei;
    int total = 2 * E;
    int samples = total < 4096 ? total : 4096;
    for (int i = threadIdx.x; i < samples; i += blockDim.x) {
        long long v = p[i];
        if (v < 0 || v >= (long long)N) ok = 0;
    }
    __syncthreads();
    if (threadIdx.x == 0) g_idx64_flag = ok;
}

// ---------------------------------------------------------------------------
// Pack W1 [512,256] into Wc [256,512]
// ---------------------------------------------------------------------------
__global__ void pack_w_kernel(const float* __restrict__ W1) {
    int idx = blockIdx.x * blockDim.x + threadIdx.x;
    if (idx >= HID * HID2) return;
    int k = idx >> 9;
    int j = idx & (HID2 - 1);
    float v = (j < HID) ? W1[k * HID + j]
                        : W1[(HID + k) * HID + (j - HID)];
    g_Wc[idx] = v;
}

// ---------------------------------------------------------------------------
// SGEMM g_AB[M,512] = z[M,256] @ g_Wc[256,512]  (+ b1 folded into cols>=256)
// 128x128 tile, BK=8, 8x8 per thread via f32x2 packed FMA.
// ---------------------------------------------------------------------------
#define BM 128
#define BN 128
#define BK 8
#define TM 8
#define TN 8

__global__ __launch_bounds__(256, 2)
void sgemm_kernel(const float* __restrict__ A, const float* __restrict__ b1, int M) {
    const int K = HID, N = HID2;
    __shared__ float As[BK][BM];
    __shared__ float Bs[BK][BN];

    int tid = threadIdx.x;
    int blockRow = blockIdx.y * BM;
    int blockCol = blockIdx.x * BN;

    int aRow = tid >> 1;
    int aCol = (tid & 1) * 4;
    int bRow = tid >> 5;
    int bCol = (tid & 31) * 4;

    int tRow = (tid >> 4) * TM;
    int tCol = (tid & 15) * TN;

    // acc2[i][j] holds columns (tCol+2j, tCol+2j+1) for row tRow+i
    unsigned long long acc2[TM][TN / 2];
#pragma unroll
    for (int i = 0; i < TM; i++)
#pragma unroll
        for (int j = 0; j < TN / 2; j++) acc2[i][j] = 0ull;

    for (int k0 = 0; k0 < K; k0 += BK) {
        int gRow = blockRow + aRow;
        float4 av = make_float4(0.f, 0.f, 0.f, 0.f);
        if (gRow < M)
            av = *reinterpret_cast<const float4*>(A + (size_t)gRow * K + k0 + aCol);
        As[aCol + 0][aRow] = av.x;
        As[aCol + 1][aRow] = av.y;
        As[aCol + 2][aRow] = av.z;
        As[aCol + 3][aRow] = av.w;

        float4 bv = *reinterpret_cast<const float4*>(
            g_Wc + (size_t)(k0 + bRow) * N + blockCol + bCol);
        *reinterpret_cast<float4*>(&Bs[bRow][bCol]) = bv;

        __syncthreads();

#pragma unroll
        for (int k = 0; k < BK; k++) {
            // N-operand: 4 packed pairs straight out of shared (no repack)
            unsigned long long nn[TN / 2];
            {
                ulonglong2 p0 = *reinterpret_cast<const ulonglong2*>(&Bs[k][tCol]);
                ulonglong2 p1 = *reinterpret_cast<const ulonglong2*>(&Bs[k][tCol + 4]);
                nn[0] = p0.x; nn[1] = p0.y; nn[2] = p1.x; nn[3] = p1.y;
            }
            // M-operand: 8 scalars, duplicated into pairs
            float m[TM];
            {
                float4 v0 = *reinterpret_cast<const float4*>(&As[k][tRow]);
                float4 v1 = *reinterpret_cast<const float4*>(&As[k][tRow + 4]);
                m[0] = v0.x; m[1] = v0.y; m[2] = v0.z; m[3] = v0.w;
                m[4] = v1.x; m[5] = v1.y; m[6] = v1.z; m[7] = v1.w;
            }
#pragma unroll
            for (int i = 0; i < TM; i++) {
                unsigned long long mm = fdup2(m[i]);
#pragma unroll
                for (int j = 0; j < TN / 2; j++)
                    acc2[i][j] = ffma2(mm, nn[j], acc2[i][j]);
            }
        }
        __syncthreads();
    }

    // Epilogue: unpack, add b1 to columns >= 256, store
    int colBase = blockCol + tCol;
    float bias[TN];
#pragma unroll
    for (int j = 0; j < TN; j++) {
        int c = colBase + j;
        bias[j] = (c >= HID) ? __ldg(&b1[c - HID]) : 0.f;
    }
#pragma unroll
    for (int i = 0; i < TM; i++) {
        int gRow = blockRow + tRow + i;
        if (gRow < M) {
            float r[TN];
#pragma unroll
            for (int j = 0; j < TN / 2; j++)
                funpack2(acc2[i][j], r[2 * j], r[2 * j + 1]);
#pragma unroll
            for (int j = 0; j < TN; j++) r[j] += bias[j];
#pragma unroll
            for (int j = 0; j < TN; j += 4) {
                float4 v = make_float4(r[j], r[j + 1], r[j + 2], r[j + 3]);
                *reinterpret_cast<float4*>(
                    g_AB + (size_t)gRow * HID2 + colBase + j) = v;
            }
        }
    }
}

// ---------------------------------------------------------------------------
// Edge scores: persistent warps, W2 register-resident, b1 pre-folded.
// score[e] = sum_h relu(AB[src,h] + AB[dst,256+h]) * W2[h] + b2
// ---------------------------------------------------------------------------
#define EDGE_BLOCKS 1184
#define EDGE_THREADS 256

__global__ __launch_bounds__(EDGE_THREADS)
void edge_kernel(const void* __restrict__ ei_raw,
                 const float* __restrict__ W2,
                 const float* __restrict__ b2,
                 float* __restrict__ out,
                 int E, int M) {
    int lane = threadIdx.x & 31;
    int warp = (blockIdx.x * EDGE_THREADS + threadIdx.x) >> 5;
    int nwarps = (gridDim.x * EDGE_THREADS) >> 5;

    // Register-resident W2 (2 float4 per lane) and bias
    const float4* __restrict__ w2v = reinterpret_cast<const float4*>(W2);
    float4 w0 = __ldg(&w2v[lane]);
    float4 w1 = __ldg(&w2v[lane + 32]);
    float bias = __ldg(b2);

    int idx64 = g_idx64_flag;
    const long long* ei64 = (const long long*)ei_raw;
    const int*       ei32 = (const int*)ei_raw;

    for (int e = warp; e < E; e += nwarps) {
        long long s, d;
        if (idx64) {
            s = ei64[e];
            d = ei64[(size_t)E + e];
        } else {
            s = ei32[e];
            d = ei32[(size_t)E + e];
        }
        s = s < 0 ? 0 : (s >= M ? M - 1 : s);
        d = d < 0 ? 0 : (d >= M ? M - 1 : d);

        const float4* __restrict__ Arow =
            reinterpret_cast<const float4*>(g_AB + (size_t)s * HID2);
        const float4* __restrict__ Brow =
            reinterpret_cast<const float4*>(g_AB + (size_t)d * HID2 + HID);

        float4 a0 = __ldg(&Arow[lane]);
        float4 b0 = __ldg(&Brow[lane]);
        float4 a1 = __ldg(&Arow[lane + 32]);
        float4 b1v = __ldg(&Brow[lane + 32]);

        float acc = 0.f;
        acc = fmaf(fmaxf(a0.x + b0.x, 0.f), w0.x, acc);
        acc = fmaf(fmaxf(a0.y + b0.y, 0.f), w0.y, acc);
        acc = fmaf(fmaxf(a0.z + b0.z, 0.f), w0.z, acc);
        acc = fmaf(fmaxf(a0.w + b0.w, 0.f), w0.w, acc);
        acc = fmaf(fmaxf(a1.x + b1v.x, 0.f), w1.x, acc);
        acc = fmaf(fmaxf(a1.y + b1v.y, 0.f), w1.y, acc);
        acc = fmaf(fmaxf(a1.z + b1v.z, 0.f), w1.z, acc);
        acc = fmaf(fmaxf(a1.w + b1v.w, 0.f), w1.w, acc);

#pragma unroll
        for (int off = 16; off > 0; off >>= 1)
            acc += __shfl_xor_sync(0xFFFFFFFFu, acc, off);

        if (lane == 0)
            out[e] = acc + bias;
    }
}

// ---------------------------------------------------------------------------
// Launch
// ---------------------------------------------------------------------------
extern "C" void kernel_launch(void* const* d_in, const int* in_sizes, int n_in,
                              void* d_out, int out_size) {
    const float* z  = (const float*)d_in[0];
    const void*  ei = d_in[1];
    const float* W1 = (const float*)d_in[2];
    const float* b1 = (const float*)d_in[3];
    const float* W2 = (const float*)d_in[4];
    const float* b2 = (const float*)d_in[5];
    float* out = (float*)d_out;

    int M = in_sizes[0] / HID;   // nodes (50000)
    int E = in_sizes[1] / 2;     // edges (800000)

    probe_kernel<<<1, 256>>>(ei, E, M);
    pack_w_kernel<<<(HID * HID2 + 255) / 256, 256>>>(W1);

    dim3 grid1(HID2 / BN, (M + BM - 1) / BM);
    sgemm_kernel<<<grid1, 256>>>(z, b1, M);

    edge_kernel<<<EDGE_BLOCKS, EDGE_THREADS>>>(ei, W2, b2, out, E, M);
}

// round 4
// speedup vs baseline: 1.2209x; 1.0685x over previous
#include <cuda_runtime.h>
#include <cuda_bf16.h>
#include <cstdint>

#define HID   256
#define HID2  512
#define MAXN  50000

// Scratch: AB[n,0:256]=z@W1_top, AB[n,256:512]=z@W1_bot + b1
__device__ float g_AB[(size_t)MAXN * HID2];
// Packed weight Wc[k, j]: j<256 -> W1[k, j]; j>=256 -> W1[256+k, j-256]
__device__ float g_Wc[HID * HID2];
__device__ int g_idx64_flag;

// ---------------------------------------------------------------------------
// f32x2 packed-FMA helpers
// ---------------------------------------------------------------------------
__device__ __forceinline__ unsigned long long fdup2(float x) {
    unsigned long long r;
    asm("mov.b64 %0, {%1, %1};" : "=l"(r) : "f"(x));
    return r;
}
__device__ __forceinline__ unsigned long long ffma2(unsigned long long a,
                                                    unsigned long long b,
                                                    unsigned long long c) {
    unsigned long long d;
    asm("fma.rn.f32x2 %0, %1, %2, %3;" : "=l"(d) : "l"(a), "l"(b), "l"(c));
    return d;
}
__device__ __forceinline__ void funpack2(unsigned long long v, float& lo, float& hi) {
    asm("mov.b64 {%0, %1}, %2;" : "=f"(lo), "=f"(hi) : "l"(v));
}

// ---------------------------------------------------------------------------
// Probe edge_index dtype (int64 vs int32 on device)
// ---------------------------------------------------------------------------
__global__ void probe_kernel(const void* __restrict__ ei, int E, int N) {
    __shared__ int ok;
    if (threadIdx.x == 0) ok = 1;
    __syncthreads();
    const long long* p = (const long long*)ei;
    int total = 2 * E;
    int samples = total < 4096 ? total : 4096;
    for (int i = threadIdx.x; i < samples; i += blockDim.x) {
        long long v = p[i];
        if (v < 0 || v >= (long long)N) ok = 0;
    }
    __syncthreads();
    if (threadIdx.x == 0) g_idx64_flag = ok;
}

// ---------------------------------------------------------------------------
// Pack W1 [512,256] into Wc [256,512]
// ---------------------------------------------------------------------------
__global__ void pack_w_kernel(const float* __restrict__ W1) {
    int idx = blockIdx.x * blockDim.x + threadIdx.x;
    if (idx >= HID * HID2) return;
    int k = idx >> 9;
    int j = idx & (HID2 - 1);
    float v = (j < HID) ? W1[k * HID + j]
                        : W1[(HID + k) * HID + (j - HID)];
    g_Wc[idx] = v;
}

// ---------------------------------------------------------------------------
// SGEMM g_AB[M,512] = z[M,256] @ g_Wc[256,512]  (+ b1 folded into cols>=256)
// 128x128 tile, BK=16, double-buffered smem, 8x8/thread via f32x2.
// ---------------------------------------------------------------------------
#define BM 128
#define BN 128
#define BK 16
#define TM 8
#define TN 8
#define APAD 4   // As row padding (floats) to reduce STS transpose conflicts

__global__ __launch_bounds__(256, 2)
void sgemm_kernel(const float* __restrict__ A, const float* __restrict__ b1, int M) {
    const int K = HID, N = HID2;
    __shared__ float As[2][BK][BM + APAD];
    __shared__ float Bs[2][BK][BN];

    int tid = threadIdx.x;
    int blockRow = blockIdx.y * BM;
    int blockCol = blockIdx.x * BN;

    // A-tile load mapping: 512 float4 / 256 thr = 2 each
    int aRow0 = tid >> 2;               // 0..63   (idx = tid)
    int aK4_0 = (tid & 3) * 4;          // 0,4,8,12
    int aRow1 = (tid + 256) >> 2;       // 64..127 (idx = tid+256)
    int aK4_1 = aK4_0;                  // same low bits
    // B-tile load mapping
    int bRow0 = tid >> 5;               // 0..7
    int bCol0 = (tid & 31) * 4;
    int bRow1 = bRow0 + 8;              // 8..15
    int bCol1 = bCol0;

    int tRow = (tid >> 4) * TM;
    int tCol = (tid & 15) * TN;

    unsigned long long acc2[TM][TN / 2];
#pragma unroll
    for (int i = 0; i < TM; i++)
#pragma unroll
        for (int j = 0; j < TN / 2; j++) acc2[i][j] = 0ull;

    float4 aReg0, aReg1, bReg0, bReg1;

    // ---- prologue: load tile 0 ----
    {
        int g0 = blockRow + aRow0;
        int g1 = blockRow + aRow1;
        aReg0 = (g0 < M) ? *reinterpret_cast<const float4*>(A + (size_t)g0 * K + aK4_0)
                         : make_float4(0.f, 0.f, 0.f, 0.f);
        aReg1 = (g1 < M) ? *reinterpret_cast<const float4*>(A + (size_t)g1 * K + aK4_1)
                         : make_float4(0.f, 0.f, 0.f, 0.f);
        bReg0 = *reinterpret_cast<const float4*>(g_Wc + (size_t)bRow0 * N + blockCol + bCol0);
        bReg1 = *reinterpret_cast<const float4*>(g_Wc + (size_t)bRow1 * N + blockCol + bCol1);

        As[0][aK4_0 + 0][aRow0] = aReg0.x;
        As[0][aK4_0 + 1][aRow0] = aReg0.y;
        As[0][aK4_0 + 2][aRow0] = aReg0.z;
        As[0][aK4_0 + 3][aRow0] = aReg0.w;
        As[0][aK4_1 + 0][aRow1] = aReg1.x;
        As[0][aK4_1 + 1][aRow1] = aReg1.y;
        As[0][aK4_1 + 2][aRow1] = aReg1.z;
        As[0][aK4_1 + 3][aRow1] = aReg1.w;
        *reinterpret_cast<float4*>(&Bs[0][bRow0][bCol0]) = bReg0;
        *reinterpret_cast<float4*>(&Bs[0][bRow1][bCol1]) = bReg1;
    }
    __syncthreads();

    int buf = 0;
    const int NITER = K / BK;   // 16
#pragma unroll 1
    for (int it = 0; it < NITER; ++it) {
        int k0n = (it + 1) * BK;
        bool more = (it + 1 < NITER);

        // issue loads for next tile
        if (more) {
            int g0 = blockRow + aRow0;
            int g1 = blockRow + aRow1;
            aReg0 = (g0 < M) ? *reinterpret_cast<const float4*>(A + (size_t)g0 * K + k0n + aK4_0)
                             : make_float4(0.f, 0.f, 0.f, 0.f);
            aReg1 = (g1 < M) ? *reinterpret_cast<const float4*>(A + (size_t)g1 * K + k0n + aK4_1)
                             : make_float4(0.f, 0.f, 0.f, 0.f);
            bReg0 = *reinterpret_cast<const float4*>(g_Wc + (size_t)(k0n + bRow0) * N + blockCol + bCol0);
            bReg1 = *reinterpret_cast<const float4*>(g_Wc + (size_t)(k0n + bRow1) * N + blockCol + bCol1);
        }

        // compute on current buffer
#pragma unroll
        for (int k = 0; k < BK; k++) {
            unsigned long long nn[TN / 2];
            {
                ulonglong2 p0 = *reinterpret_cast<const ulonglong2*>(&Bs[buf][k][tCol]);
                ulonglong2 p1 = *reinterpret_cast<const ulonglong2*>(&Bs[buf][k][tCol + 4]);
                nn[0] = p0.x; nn[1] = p0.y; nn[2] = p1.x; nn[3] = p1.y;
            }
            float m[TM];
            {
                float4 v0 = *reinterpret_cast<const float4*>(&As[buf][k][tRow]);
                float4 v1 = *reinterpret_cast<const float4*>(&As[buf][k][tRow + 4]);
                m[0] = v0.x; m[1] = v0.y; m[2] = v0.z; m[3] = v0.w;
                m[4] = v1.x; m[5] = v1.y; m[6] = v1.z; m[7] = v1.w;
            }
#pragma unroll
            for (int i = 0; i < TM; i++) {
                unsigned long long mm = fdup2(m[i]);
#pragma unroll
                for (int j = 0; j < TN / 2; j++)
                    acc2[i][j] = ffma2(mm, nn[j], acc2[i][j]);
            }
        }

        // store next tile into other buffer
        if (more) {
            int nb = buf ^ 1;
            As[nb][aK4_0 + 0][aRow0] = aReg0.x;
            As[nb][aK4_0 + 1][aRow0] = aReg0.y;
            As[nb][aK4_0 + 2][aRow0] = aReg0.z;
            As[nb][aK4_0 + 3][aRow0] = aReg0.w;
            As[nb][aK4_1 + 0][aRow1] = aReg1.x;
            As[nb][aK4_1 + 1][aRow1] = aReg1.y;
            As[nb][aK4_1 + 2][aRow1] = aReg1.z;
            As[nb][aK4_1 + 3][aRow1] = aReg1.w;
            *reinterpret_cast<float4*>(&Bs[nb][bRow0][bCol0]) = bReg0;
            *reinterpret_cast<float4*>(&Bs[nb][bRow1][bCol1]) = bReg1;
        }
        __syncthreads();
        buf ^= 1;
    }

    // Epilogue: unpack, add b1 to columns >= 256, store
    int colBase = blockCol + tCol;
    float bias[TN];
#pragma unroll
    for (int j = 0; j < TN; j++) {
        int c = colBase + j;
        bias[j] = (c >= HID) ? __ldg(&b1[c - HID]) : 0.f;
    }
#pragma unroll
    for (int i = 0; i < TM; i++) {
        int gRow = blockRow + tRow + i;
        if (gRow < M) {
            float r[TN];
#pragma unroll
            for (int j = 0; j < TN / 2; j++)
                funpack2(acc2[i][j], r[2 * j], r[2 * j + 1]);
#pragma unroll
            for (int j = 0; j < TN; j++) r[j] += bias[j];
#pragma unroll
            for (int j = 0; j < TN; j += 4) {
                float4 v = make_float4(r[j], r[j + 1], r[j + 2], r[j + 3]);
                *reinterpret_cast<float4*>(
                    g_AB + (size_t)gRow * HID2 + colBase + j) = v;
            }
        }
    }
}

// ---------------------------------------------------------------------------
// Edge scores: persistent warps, W2 register-resident, b1 pre-folded.
// ---------------------------------------------------------------------------
#define EDGE_BLOCKS 1184
#define EDGE_THREADS 256

__global__ __launch_bounds__(EDGE_THREADS)
void edge_kernel(const void* __restrict__ ei_raw,
                 const float* __restrict__ W2,
                 const float* __restrict__ b2,
                 float* __restrict__ out,
                 int E, int M) {
    int lane = threadIdx.x & 31;
    int warp = (blockIdx.x * EDGE_THREADS + threadIdx.x) >> 5;
    int nwarps = (gridDim.x * EDGE_THREADS) >> 5;

    const float4* __restrict__ w2v = reinterpret_cast<const float4*>(W2);
    float4 w0 = __ldg(&w2v[lane]);
    float4 w1 = __ldg(&w2v[lane + 32]);
    float bias = __ldg(b2);

    int idx64 = g_idx64_flag;
    const long long* ei64 = (const long long*)ei_raw;
    const int*       ei32 = (const int*)ei_raw;

    for (int e = warp; e < E; e += nwarps) {
        long long s, d;
        if (idx64) {
            s = ei64[e];
            d = ei64[(size_t)E + e];
        } else {
            s = ei32[e];
            d = ei32[(size_t)E + e];
        }
        s = s < 0 ? 0 : (s >= M ? M - 1 : s);
        d = d < 0 ? 0 : (d >= M ? M - 1 : d);

        const float4* __restrict__ Arow =
            reinterpret_cast<const float4*>(g_AB + (size_t)s * HID2);
        const float4* __restrict__ Brow =
            reinterpret_cast<const float4*>(g_AB + (size_t)d * HID2 + HID);

        float4 a0 = __ldg(&Arow[lane]);
        float4 b0 = __ldg(&Brow[lane]);
        float4 a1 = __ldg(&Arow[lane + 32]);
        float4 b1v = __ldg(&Brow[lane + 32]);

        float acc = 0.f;
        acc = fmaf(fmaxf(a0.x + b0.x, 0.f), w0.x, acc);
        acc = fmaf(fmaxf(a0.y + b0.y, 0.f), w0.y, acc);
        acc = fmaf(fmaxf(a0.z + b0.z, 0.f), w0.z, acc);
        acc = fmaf(fmaxf(a0.w + b0.w, 0.f), w0.w, acc);
        acc = fmaf(fmaxf(a1.x + b1v.x, 0.f), w1.x, acc);
        acc = fmaf(fmaxf(a1.y + b1v.y, 0.f), w1.y, acc);
        acc = fmaf(fmaxf(a1.z + b1v.z, 0.f), w1.z, acc);
        acc = fmaf(fmaxf(a1.w + b1v.w, 0.f), w1.w, acc);

#pragma unroll
        for (int off = 16; off > 0; off >>= 1)
            acc += __shfl_xor_sync(0xFFFFFFFFu, acc, off);

        if (lane == 0)
            out[e] = acc + bias;
    }
}

// ---------------------------------------------------------------------------
// Launch
// ---------------------------------------------------------------------------
extern "C" void kernel_launch(void* const* d_in, const int* in_sizes, int n_in,
                              void* d_out, int out_size) {
    const float* z  = (const float*)d_in[0];
    const void*  ei = d_in[1];
    const float* W1 = (const float*)d_in[2];
    const float* b1 = (const float*)d_in[3];
    const float* W2 = (const float*)d_in[4];
    const float* b2 = (const float*)d_in[5];
    float* out = (float*)d_out;

    int M = in_sizes[0] / HID;   // nodes (50000)
    int E = in_sizes[1] / 2;     // edges (800000)

    probe_kernel<<<1, 256>>>(ei, E, M);
    pack_w_kernel<<<(HID * HID2 + 255) / 256, 256>>>(W1);

    dim3 grid1(HID2 / BN, (M + BM - 1) / BM);
    sgemm_kernel<<<grid1, 256>>>(z, b1, M);

    edge_kernel<<<EDGE_BLOCKS, EDGE_THREADS>>>(ei, W2, b2, out, E, M);
}

// round 6
// speedup vs baseline: 1.9155x; 1.5690x over previous
#include <cuda_runtime.h>
#include <cuda_bf16.h>
#include <cstdint>

#define HID   256
#define HID2  512
#define MAXN  50000

// Scratch
__device__ float g_AB[(size_t)MAXN * HID2];
__device__ __nv_bfloat16 g_Wt_hi[HID2 * HID];   // [n][k], k-contiguous
__device__ __nv_bfloat16 g_Wt_lo[HID2 * HID];
__device__ __nv_bfloat16 g_Z_hi[(size_t)MAXN * HID];
__device__ __nv_bfloat16 g_Z_lo[(size_t)MAXN * HID];
__device__ int g_idx64_flag;

// ---------------------------------------------------------------------------
// helpers
// ---------------------------------------------------------------------------
__device__ __forceinline__ uint32_t smem_u32(const void* p) {
    uint32_t a;
    asm("{ .reg .u64 t; cvta.to.shared.u64 t, %1; cvt.u32.u64 %0, t; }"
        : "=r"(a) : "l"(p));
    return a;
}
__device__ __forceinline__ void cp16(uint32_t s, const void* g) {
    asm volatile("cp.async.cg.shared.global [%0], [%1], 16;" :: "r"(s), "l"(g) : "memory");
}
__device__ __forceinline__ void ldsm_x4(uint32_t* r, uint32_t a) {
    asm volatile("ldmatrix.sync.aligned.m8n8.x4.shared.b16 {%0,%1,%2,%3}, [%4];"
                 : "=r"(r[0]), "=r"(r[1]), "=r"(r[2]), "=r"(r[3]) : "r"(a));
}
__device__ __forceinline__ void ldsm_x2(uint32_t* r, uint32_t a) {
    asm volatile("ldmatrix.sync.aligned.m8n8.x2.shared.b16 {%0,%1}, [%2];"
                 : "=r"(r[0]), "=r"(r[1]) : "r"(a));
}
__device__ __forceinline__ void mma_bf16(float* c, const uint32_t* a, const uint32_t* b) {
    asm volatile("mma.sync.aligned.m16n8k16.row.col.f32.bf16.bf16.f32 "
                 "{%0,%1,%2,%3}, {%4,%5,%6,%7}, {%8,%9}, {%0,%1,%2,%3};"
                 : "+f"(c[0]), "+f"(c[1]), "+f"(c[2]), "+f"(c[3])
                 : "r"(a[0]), "r"(a[1]), "r"(a[2]), "r"(a[3]), "r"(b[0]), "r"(b[1]));
}
// swizzled byte offset inside a [128 row][64 bf16] tile (row pitch 128B)
__device__ __forceinline__ uint32_t swz(int r, int kb) {
    return ((uint32_t)(r * 128 + kb)) ^ ((uint32_t)(r & 7) << 4);
}

// ---------------------------------------------------------------------------
// Probe edge_index dtype (int64 vs int32 on device)
// ---------------------------------------------------------------------------
__global__ void probe_kernel(const void* __restrict__ ei, int E, int N) {
    __shared__ int ok;
    if (threadIdx.x == 0) ok = 1;
    __syncthreads();
    const long long* p = (const long long*)ei;
    int total = 2 * E;
    int samples = total < 4096 ? total : 4096;
    for (int i = threadIdx.x; i < samples; i += blockDim.x) {
        long long v = p[i];
        if (v < 0 || v >= (long long)N) ok = 0;
    }
    __syncthreads();
    if (threadIdx.x == 0) g_idx64_flag = ok;
}

// ---------------------------------------------------------------------------
// Pack W1 [512,256] -> transposed split bf16 Wt_hi/Wt_lo [n=512][k=256]
// ---------------------------------------------------------------------------
__global__ void pack_w_kernel(const float* __restrict__ W1) {
    int idx = blockIdx.x * blockDim.x + threadIdx.x;
    if (idx >= HID2 * HID) return;
    int n = idx >> 8;
    int k = idx & (HID - 1);
    float v = (n < HID) ? W1[k * HID + n]
                        : W1[(HID + k) * HID + (n - HID)];
    __nv_bfloat16 hi = __float2bfloat16(v);
    float r = v - __bfloat162float(hi);
    g_Wt_hi[idx] = hi;
    g_Wt_lo[idx] = __float2bfloat16(r);
}

// ---------------------------------------------------------------------------
// Split z fp32 -> z_hi/z_lo bf16 (8 elems per thread)
// ---------------------------------------------------------------------------
__global__ void split_z_kernel(const float* __restrict__ z, int M) {
    int idx = blockIdx.x * blockDim.x + threadIdx.x;
    int total = M * HID / 8;
    if (idx >= total) return;
    const float4* p = reinterpret_cast<const float4*>(z) + (size_t)idx * 2;
    float4 v0 = p[0], v1 = p[1];
    float f[8] = {v0.x, v0.y, v0.z, v0.w, v1.x, v1.y, v1.z, v1.w};
    __nv_bfloat16 hi[8], lo[8];
#pragma unroll
    for (int i = 0; i < 8; i++) {
        hi[i] = __float2bfloat16(f[i]);
        lo[i] = __float2bfloat16(f[i] - __bfloat162float(hi[i]));
    }
    *reinterpret_cast<uint4*>(&g_Z_hi[(size_t)idx * 8]) = *reinterpret_cast<uint4*>(hi);
    *reinterpret_cast<uint4*>(&g_Z_lo[(size_t)idx * 8]) = *reinterpret_cast<uint4*>(lo);
}

// ---------------------------------------------------------------------------
// HMMA GEMM: g_AB[M,512] = z[M,256] @ W (+ b1 on cols>=256)
// bf16 split: D = Ahi*Bhi + Ahi*Blo + Alo*Bhi, fp32 accum.
// 128x128 tile/CTA, 8 warps (2m x 4n), K chunks of 64, cp.async 2-stage.
// ---------------------------------------------------------------------------
#define KC 64
#define STAGE_BYTES 65536   // 4 tiles x 16KB
#define OFF_AHI 0
#define OFF_ALO 16384
#define OFF_BHI 32768
#define OFF_BLO 49152
#define SMEM_DYN (2 * STAGE_BYTES)

__global__ __launch_bounds__(256, 1)
void hmma_kernel(const float* __restrict__ b1, int M) {
    extern __shared__ char smem[];
    uint32_t sb = smem_u32(smem);
    int tid = threadIdx.x;
    int wid = tid >> 5;
    int lane = tid & 31;
    int mBase = blockIdx.y * 128;
    int nBase = blockIdx.x * 128;
    int warpM = wid >> 2;     // 0..1
    int warpN = wid & 3;      // 0..3

    float c[4][4][4];
#pragma unroll
    for (int i = 0; i < 4; i++)
#pragma unroll
        for (int j = 0; j < 4; j++)
#pragma unroll
            for (int q = 0; q < 4; q++) c[i][j][q] = 0.f;

    // stage loader: issues 4096 x 16B cp.async (4 tiles x 1024 vectors)
    auto load_stage = [&](int s, int kc) {
        uint32_t base = sb + s * STAGE_BYTES;
        int kOff = kc * KC;
#pragma unroll
        for (int i = 0; i < 4; i++) {
            int idx = tid + i * 256;      // 0..1023
            int r = idx >> 3;             // 0..127
            int kg = idx & 7;             // 16B group
            uint32_t sw = swz(r, kg * 16);
            int ar = mBase + r;
            ar = ar < M ? ar : M - 1;
            size_t aoff = (size_t)ar * HID + kOff + kg * 8;
            size_t boff = (size_t)(nBase + r) * HID + kOff + kg * 8;
            cp16(base + OFF_AHI + sw, &g_Z_hi[aoff]);
            cp16(base + OFF_ALO + sw, &g_Z_lo[aoff]);
            cp16(base + OFF_BHI + sw, &g_Wt_hi[boff]);
            cp16(base + OFF_BLO + sw, &g_Wt_lo[boff]);
        }
        asm volatile("cp.async.commit_group;" ::: "memory");
    };

    load_stage(0, 0);
    load_stage(1, 1);

#pragma unroll 1
    for (int ck = 0; ck < 4; ck++) {
        if (ck < 3) asm volatile("cp.async.wait_group 1;" ::: "memory");
        else        asm volatile("cp.async.wait_group 0;" ::: "memory");
        __syncthreads();

        uint32_t base = sb + (ck & 1) * STAGE_BYTES;
#pragma unroll
        for (int ks = 0; ks < 4; ks++) {
            uint32_t ahi[4][4], alo[4][4], bhi[4][2], blo[4][2];
#pragma unroll
            for (int mf = 0; mf < 4; mf++) {
                int r = warpM * 64 + mf * 16 + (lane & 15);
                int kb = ks * 32 + ((lane >> 4) << 4);
                uint32_t sw = swz(r, kb);
                ldsm_x4(ahi[mf], base + OFF_AHI + sw);
                ldsm_x4(alo[mf], base + OFF_ALO + sw);
            }
#pragma unroll
            for (int nf = 0; nf < 4; nf++) {
                int l = lane & 15;
                int r = warpN * 32 + nf * 8 + (l & 7);
                int kb = ks * 32 + ((l >> 3) << 4);
                uint32_t sw = swz(r, kb);
                ldsm_x2(bhi[nf], base + OFF_BHI + sw);
                ldsm_x2(blo[nf], base + OFF_BLO + sw);
            }
#pragma unroll
            for (int mf = 0; mf < 4; mf++)
#pragma unroll
                for (int nf = 0; nf < 4; nf++) {
                    mma_bf16(c[mf][nf], ahi[mf], bhi[nf]);
                    mma_bf16(c[mf][nf], ahi[mf], blo[nf]);
                    mma_bf16(c[mf][nf], alo[mf], bhi[nf]);
                }
        }
        __syncthreads();
        if (ck + 2 < 4) load_stage(ck & 1, ck + 2);
    }

    // epilogue
    int rowInFrag = lane >> 2;
    int colInFrag = (lane & 3) * 2;
#pragma unroll
    for (int nf = 0; nf < 4; nf++) {
        int col = nBase + warpN * 32 + nf * 8 + colInFrag;
        float bx = 0.f, by = 0.f;
        if (col >= HID) {
            bx = __ldg(&b1[col - HID]);
            by = __ldg(&b1[col - HID + 1]);
        }
#pragma unroll
        for (int mf = 0; mf < 4; mf++) {
            int row0 = mBase + warpM * 64 + mf * 16 + rowInFrag;
            if (row0 < M) {
                float2 v = make_float2(c[mf][nf][0] + bx, c[mf][nf][1] + by);
                *reinterpret_cast<float2*>(&g_AB[(size_t)row0 * HID2 + col]) = v;
            }
            int row1 = row0 + 8;
            if (row1 < M) {
                float2 v = make_float2(c[mf][nf][2] + bx, c[mf][nf][3] + by);
                *reinterpret_cast<float2*>(&g_AB[(size_t)row1 * HID2 + col]) = v;
            }
        }
    }
}

// ---------------------------------------------------------------------------
// Edge scores: persistent warps, W2 register-resident, b1 pre-folded.
// ---------------------------------------------------------------------------
#define EDGE_BLOCKS 1184
#define EDGE_THREADS 256

__global__ __launch_bounds__(EDGE_THREADS)
void edge_kernel(const void* __restrict__ ei_raw,
                 const float* __restrict__ W2,
                 const float* __restrict__ b2,
                 float* __restrict__ out,
                 int E, int M) {
    int lane = threadIdx.x & 31;
    int warp = (blockIdx.x * EDGE_THREADS + threadIdx.x) >> 5;
    int nwarps = (gridDim.x * EDGE_THREADS) >> 5;

    const float4* __restrict__ w2v = reinterpret_cast<const float4*>(W2);
    float4 w0 = __ldg(&w2v[lane]);
    float4 w1 = __ldg(&w2v[lane + 32]);
    float bias = __ldg(b2);

    int idx64 = g_idx64_flag;
    const long long* ei64 = (const long long*)ei_raw;
    const int*       ei32 = (const int*)ei_raw;

    for (int e = warp; e < E; e += nwarps) {
        long long s, d;
        if (idx64) {
            s = ei64[e];
            d = ei64[(size_t)E + e];
        } else {
            s = ei32[e];
            d = ei32[(size_t)E + e];
        }
        s = s < 0 ? 0 : (s >= M ? M - 1 : s);
        d = d < 0 ? 0 : (d >= M ? M - 1 : d);

        const float4* __restrict__ Arow =
            reinterpret_cast<const float4*>(g_AB + (size_t)s * HID2);
        const float4* __restrict__ Brow =
            reinterpret_cast<const float4*>(g_AB + (size_t)d * HID2 + HID);

        float4 a0 = __ldg(&Arow[lane]);
        float4 b0 = __ldg(&Brow[lane]);
        float4 a1 = __ldg(&Arow[lane + 32]);
        float4 b1v = __ldg(&Brow[lane + 32]);

        float acc = 0.f;
        acc = fmaf(fmaxf(a0.x + b0.x, 0.f), w0.x, acc);
        acc = fmaf(fmaxf(a0.y + b0.y, 0.f), w0.y, acc);
        acc = fmaf(fmaxf(a0.z + b0.z, 0.f), w0.z, acc);
        acc = fmaf(fmaxf(a0.w + b0.w, 0.f), w0.w, acc);
        acc = fmaf(fmaxf(a1.x + b1v.x, 0.f), w1.x, acc);
        acc = fmaf(fmaxf(a1.y + b1v.y, 0.f), w1.y, acc);
        acc = fmaf(fmaxf(a1.z + b1v.z, 0.f), w1.z, acc);
        acc = fmaf(fmaxf(a1.w + b1v.w, 0.f), w1.w, acc);

#pragma unroll
        for (int off = 16; off > 0; off >>= 1)
            acc += __shfl_xor_sync(0xFFFFFFFFu, acc, off);

        if (lane == 0)
            out[e] = acc + bias;
    }
}

// ---------------------------------------------------------------------------
// Launch
// ---------------------------------------------------------------------------
extern "C" void kernel_launch(void* const* d_in, const int* in_sizes, int n_in,
                              void* d_out, int out_size) {
    const float* z  = (const float*)d_in[0];
    const void*  ei = d_in[1];
    const float* W1 = (const float*)d_in[2];
    const float* b1 = (const float*)d_in[3];
    const float* W2 = (const float*)d_in[4];
    const float* b2 = (const float*)d_in[5];
    float* out = (float*)d_out;

    int M = in_sizes[0] / HID;   // nodes (50000)
    int E = in_sizes[1] / 2;     // edges (800000)

    probe_kernel<<<1, 256>>>(ei, E, M);
    pack_w_kernel<<<(HID2 * HID + 255) / 256, 256>>>(W1);
    split_z_kernel<<<(M * HID / 8 + 255) / 256, 256>>>(z, M);

    static int smem_set = 0;
    if (!smem_set) {
        cudaFuncSetAttribute(hmma_kernel,
                             cudaFuncAttributeMaxDynamicSharedMemorySize, SMEM_DYN);
        smem_set = 1;
    }
    dim3 grid(HID2 / 128, (M + 127) / 128);
    hmma_kernel<<<grid, 256, SMEM_DYN>>>(b1, M);

    edge_kernel<<<EDGE_BLOCKS, EDGE_THREADS>>>(ei, W2, b2, out, E, M);
}

// round 7
// speedup vs baseline: 2.2722x; 1.1862x over previous
#include <cuda_runtime.h>
#include <cuda_bf16.h>
#include <cuda_fp16.h>
#include <cstdint>

#define HID   256
#define HID2  512
#define MAXN  50000

// Scratch
__device__ __half g_ABh[(size_t)MAXN * HID2];   // fp16 activations (b1 folded)
__device__ __nv_bfloat16 g_Wt_hi[HID2 * HID];   // [n][k], k-contiguous
__device__ __nv_bfloat16 g_Wt_lo[HID2 * HID];
__device__ __nv_bfloat16 g_Z_hi[(size_t)MAXN * HID];
__device__ __nv_bfloat16 g_Z_lo[(size_t)MAXN * HID];
__device__ int g_idx64_flag;

// ---------------------------------------------------------------------------
// helpers
// ---------------------------------------------------------------------------
__device__ __forceinline__ uint32_t smem_u32(const void* p) {
    uint32_t a;
    asm("{ .reg .u64 t; cvta.to.shared.u64 t, %1; cvt.u32.u64 %0, t; }"
        : "=r"(a) : "l"(p));
    return a;
}
__device__ __forceinline__ void cp16(uint32_t s, const void* g) {
    asm volatile("cp.async.cg.shared.global [%0], [%1], 16;" :: "r"(s), "l"(g) : "memory");
}
__device__ __forceinline__ void ldsm_x4(uint32_t* r, uint32_t a) {
    asm volatile("ldmatrix.sync.aligned.m8n8.x4.shared.b16 {%0,%1,%2,%3}, [%4];"
                 : "=r"(r[0]), "=r"(r[1]), "=r"(r[2]), "=r"(r[3]) : "r"(a));
}
__device__ __forceinline__ void ldsm_x2(uint32_t* r, uint32_t a) {
    asm volatile("ldmatrix.sync.aligned.m8n8.x2.shared.b16 {%0,%1}, [%2];"
                 : "=r"(r[0]), "=r"(r[1]) : "r"(a));
}
__device__ __forceinline__ void mma_bf16(float* c, const uint32_t* a, const uint32_t* b) {
    asm volatile("mma.sync.aligned.m16n8k16.row.col.f32.bf16.bf16.f32 "
                 "{%0,%1,%2,%3}, {%4,%5,%6,%7}, {%8,%9}, {%0,%1,%2,%3};"
                 : "+f"(c[0]), "+f"(c[1]), "+f"(c[2]), "+f"(c[3])
                 : "r"(a[0]), "r"(a[1]), "r"(a[2]), "r"(a[3]), "r"(b[0]), "r"(b[1]));
}
__device__ __forceinline__ uint32_t swz(int r, int kb) {
    return ((uint32_t)(r * 128 + kb)) ^ ((uint32_t)(r & 7) << 4);
}

// ---------------------------------------------------------------------------
// Probe edge_index dtype (int64 vs int32 on device)
// ---------------------------------------------------------------------------
__global__ void probe_kernel(const void* __restrict__ ei, int E, int N) {
    __shared__ int ok;
    if (threadIdx.x == 0) ok = 1;
    __syncthreads();
    const long long* p = (const long long*)ei;
    int total = 2 * E;
    int samples = total < 4096 ? total : 4096;
    for (int i = threadIdx.x; i < samples; i += blockDim.x) {
        long long v = p[i];
        if (v < 0 || v >= (long long)N) ok = 0;
    }
    __syncthreads();
    if (threadIdx.x == 0) g_idx64_flag = ok;
}

// ---------------------------------------------------------------------------
// Pack W1 [512,256] -> transposed split bf16 Wt_hi/Wt_lo [n=512][k=256]
// ---------------------------------------------------------------------------
__global__ void pack_w_kernel(const float* __restrict__ W1) {
    int idx = blockIdx.x * blockDim.x + threadIdx.x;
    if (idx >= HID2 * HID) return;
    int n = idx >> 8;
    int k = idx & (HID - 1);
    float v = (n < HID) ? W1[k * HID + n]
                        : W1[(HID + k) * HID + (n - HID)];
    __nv_bfloat16 hi = __float2bfloat16(v);
    float r = v - __bfloat162float(hi);
    g_Wt_hi[idx] = hi;
    g_Wt_lo[idx] = __float2bfloat16(r);
}

// ---------------------------------------------------------------------------
// Split z fp32 -> z_hi/z_lo bf16
// ---------------------------------------------------------------------------
__global__ void split_z_kernel(const float* __restrict__ z, int M) {
    int idx = blockIdx.x * blockDim.x + threadIdx.x;
    int total = M * HID / 8;
    if (idx >= total) return;
    const float4* p = reinterpret_cast<const float4*>(z) + (size_t)idx * 2;
    float4 v0 = p[0], v1 = p[1];
    float f[8] = {v0.x, v0.y, v0.z, v0.w, v1.x, v1.y, v1.z, v1.w};
    __nv_bfloat16 hi[8], lo[8];
#pragma unroll
    for (int i = 0; i < 8; i++) {
        hi[i] = __float2bfloat16(f[i]);
        lo[i] = __float2bfloat16(f[i] - __bfloat162float(hi[i]));
    }
    *reinterpret_cast<uint4*>(&g_Z_hi[(size_t)idx * 8]) = *reinterpret_cast<uint4*>(hi);
    *reinterpret_cast<uint4*>(&g_Z_lo[(size_t)idx * 8]) = *reinterpret_cast<uint4*>(lo);
}

// ---------------------------------------------------------------------------
// HMMA GEMM: AB[M,512] = z[M,256] @ W (+ b1 on cols>=256), fp16 output.
// bf16 split: D = Ahi*Bhi + Ahi*Blo + Alo*Bhi, fp32 accum.
// 128x128 tile/CTA, 8 warps (2m x 4n), K chunks of 64, cp.async 2-stage.
// ---------------------------------------------------------------------------
#define KC 64
#define STAGE_BYTES 65536
#define OFF_AHI 0
#define OFF_ALO 16384
#define OFF_BHI 32768
#define OFF_BLO 49152
#define SMEM_DYN (2 * STAGE_BYTES)

__global__ __launch_bounds__(256, 1)
void hmma_kernel(const float* __restrict__ b1, int M) {
    extern __shared__ char smem[];
    uint32_t sb = smem_u32(smem);
    int tid = threadIdx.x;
    int wid = tid >> 5;
    int lane = tid & 31;
    int mBase = blockIdx.y * 128;
    int nBase = blockIdx.x * 128;
    int warpM = wid >> 2;
    int warpN = wid & 3;

    float c[4][4][4];
#pragma unroll
    for (int i = 0; i < 4; i++)
#pragma unroll
        for (int j = 0; j < 4; j++)
#pragma unroll
            for (int q = 0; q < 4; q++) c[i][j][q] = 0.f;

    auto load_stage = [&](int s, int kc) {
        uint32_t base = sb + s * STAGE_BYTES;
        int kOff = kc * KC;
#pragma unroll
        for (int i = 0; i < 4; i++) {
            int idx = tid + i * 256;
            int r = idx >> 3;
            int kg = idx & 7;
            uint32_t sw = swz(r, kg * 16);
            int ar = mBase + r;
            ar = ar < M ? ar : M - 1;
            size_t aoff = (size_t)ar * HID + kOff + kg * 8;
            size_t boff = (size_t)(nBase + r) * HID + kOff + kg * 8;
            cp16(base + OFF_AHI + sw, &g_Z_hi[aoff]);
            cp16(base + OFF_ALO + sw, &g_Z_lo[aoff]);
            cp16(base + OFF_BHI + sw, &g_Wt_hi[boff]);
            cp16(base + OFF_BLO + sw, &g_Wt_lo[boff]);
        }
        asm volatile("cp.async.commit_group;" ::: "memory");
    };

    load_stage(0, 0);
    load_stage(1, 1);

#pragma unroll 1
    for (int ck = 0; ck < 4; ck++) {
        if (ck < 3) asm volatile("cp.async.wait_group 1;" ::: "memory");
        else        asm volatile("cp.async.wait_group 0;" ::: "memory");
        __syncthreads();

        uint32_t base = sb + (ck & 1) * STAGE_BYTES;
#pragma unroll
        for (int ks = 0; ks < 4; ks++) {
            uint32_t ahi[4][4], alo[4][4], bhi[4][2], blo[4][2];
#pragma unroll
            for (int mf = 0; mf < 4; mf++) {
                int r = warpM * 64 + mf * 16 + (lane & 15);
                int kb = ks * 32 + ((lane >> 4) << 4);
                uint32_t sw = swz(r, kb);
                ldsm_x4(ahi[mf], base + OFF_AHI + sw);
                ldsm_x4(alo[mf], base + OFF_ALO + sw);
            }
#pragma unroll
            for (int nf = 0; nf < 4; nf++) {
                int l = lane & 15;
                int r = warpN * 32 + nf * 8 + (l & 7);
                int kb = ks * 32 + ((l >> 3) << 4);
                uint32_t sw = swz(r, kb);
                ldsm_x2(bhi[nf], base + OFF_BHI + sw);
                ldsm_x2(blo[nf], base + OFF_BLO + sw);
            }
#pragma unroll
            for (int mf = 0; mf < 4; mf++)
#pragma unroll
                for (int nf = 0; nf < 4; nf++) {
                    mma_bf16(c[mf][nf], ahi[mf], bhi[nf]);
                    mma_bf16(c[mf][nf], ahi[mf], blo[nf]);
                    mma_bf16(c[mf][nf], alo[mf], bhi[nf]);
                }
        }
        __syncthreads();
        if (ck + 2 < 4) load_stage(ck & 1, ck + 2);
    }

    // epilogue: +bias on cols>=256, convert to fp16, store half2
    int rowInFrag = lane >> 2;
    int colInFrag = (lane & 3) * 2;
#pragma unroll
    for (int nf = 0; nf < 4; nf++) {
        int col = nBase + warpN * 32 + nf * 8 + colInFrag;
        float bx = 0.f, by = 0.f;
        if (col >= HID) {
            bx = __ldg(&b1[col - HID]);
            by = __ldg(&b1[col - HID + 1]);
        }
#pragma unroll
        for (int mf = 0; mf < 4; mf++) {
            int row0 = mBase + warpM * 64 + mf * 16 + rowInFrag;
            if (row0 < M) {
                __half2 h = __floats2half2_rn(c[mf][nf][0] + bx, c[mf][nf][1] + by);
                *reinterpret_cast<__half2*>(&g_ABh[(size_t)row0 * HID2 + col]) = h;
            }
            int row1 = row0 + 8;
            if (row1 < M) {
                __half2 h = __floats2half2_rn(c[mf][nf][2] + bx, c[mf][nf][3] + by);
                *reinterpret_cast<__half2*>(&g_ABh[(size_t)row1 * HID2 + col]) = h;
            }
        }
    }
}

// ---------------------------------------------------------------------------
// Edge scores: fp16 AB gather (8 halves/lane/row), fp32 math.
// ---------------------------------------------------------------------------
#define EDGE_BLOCKS 1184
#define EDGE_THREADS 256

__global__ __launch_bounds__(EDGE_THREADS)
void edge_kernel(const void* __restrict__ ei_raw,
                 const float* __restrict__ W2,
                 const float* __restrict__ b2,
                 float* __restrict__ out,
                 int E, int M) {
    int lane = threadIdx.x & 31;
    int warp = (blockIdx.x * EDGE_THREADS + threadIdx.x) >> 5;
    int nwarps = (gridDim.x * EDGE_THREADS) >> 5;

    // lane owns h in [lane*8, lane*8+8)
    const float4* w2v = reinterpret_cast<const float4*>(W2);
    float4 wA = __ldg(&w2v[2 * lane]);
    float4 wB = __ldg(&w2v[2 * lane + 1]);
    float bias = __ldg(b2);

    int idx64 = g_idx64_flag;
    const long long* ei64 = (const long long*)ei_raw;
    const int*       ei32 = (const int*)ei_raw;

    for (int e = warp; e < E; e += nwarps) {
        long long s, d;
        if (idx64) {
            s = ei64[e];
            d = ei64[(size_t)E + e];
        } else {
            s = ei32[e];
            d = ei32[(size_t)E + e];
        }
        s = s < 0 ? 0 : (s >= M ? M - 1 : s);
        d = d < 0 ? 0 : (d >= M ? M - 1 : d);

        const uint4* Arow = reinterpret_cast<const uint4*>(g_ABh + (size_t)s * HID2);
        const uint4* Brow = reinterpret_cast<const uint4*>(g_ABh + (size_t)d * HID2 + HID);

        uint4 av = __ldg(&Arow[lane]);
        uint4 bv = __ldg(&Brow[lane]);
        const __half2* ah = reinterpret_cast<const __half2*>(&av);
        const __half2* bh = reinterpret_cast<const __half2*>(&bv);

        float2 a0 = __half22float2(ah[0]), b0 = __half22float2(bh[0]);
        float2 a1 = __half22float2(ah[1]), b1p = __half22float2(bh[1]);
        float2 a2 = __half22float2(ah[2]), b2p = __half22float2(bh[2]);
        float2 a3 = __half22float2(ah[3]), b3p = __half22float2(bh[3]);

        float acc = 0.f;
        acc = fmaf(fmaxf(a0.x + b0.x, 0.f), wA.x, acc);
        acc = fmaf(fmaxf(a0.y + b0.y, 0.f), wA.y, acc);
        acc = fmaf(fmaxf(a1.x + b1p.x, 0.f), wA.z, acc);
        acc = fmaf(fmaxf(a1.y + b1p.y, 0.f), wA.w, acc);
        acc = fmaf(fmaxf(a2.x + b2p.x, 0.f), wB.x, acc);
        acc = fmaf(fmaxf(a2.y + b2p.y, 0.f), wB.y, acc);
        acc = fmaf(fmaxf(a3.x + b3p.x, 0.f), wB.z, acc);
        acc = fmaf(fmaxf(a3.y + b3p.y, 0.f), wB.w, acc);

#pragma unroll
        for (int off = 16; off > 0; off >>= 1)
            acc += __shfl_xor_sync(0xFFFFFFFFu, acc, off);

        if (lane == 0)
            out[e] = acc + bias;
    }
}

// ---------------------------------------------------------------------------
// Launch
// ---------------------------------------------------------------------------
extern "C" void kernel_launch(void* const* d_in, const int* in_sizes, int n_in,
                              void* d_out, int out_size) {
    const float* z  = (const float*)d_in[0];
    const void*  ei = d_in[1];
    const float* W1 = (const float*)d_in[2];
    const float* b1 = (const float*)d_in[3];
    const float* W2 = (const float*)d_in[4];
    const float* b2 = (const float*)d_in[5];
    float* out = (float*)d_out;

    int M = in_sizes[0] / HID;   // nodes (50000)
    int E = in_sizes[1] / 2;     // edges (800000)

    probe_kernel<<<1, 256>>>(ei, E, M);
    pack_w_kernel<<<(HID2 * HID + 255) / 256, 256>>>(W1);
    split_z_kernel<<<(M * HID / 8 + 255) / 256, 256>>>(z, M);

    static int smem_set = 0;
    if (!smem_set) {
        cudaFuncSetAttribute(hmma_kernel,
                             cudaFuncAttributeMaxDynamicSharedMemorySize, SMEM_DYN);
        smem_set = 1;
    }
    dim3 grid(HID2 / 128, (M + 127) / 128);
    hmma_kernel<<<grid, 256, SMEM_DYN>>>(b1, M);

    edge_kernel<<<EDGE_BLOCKS, EDGE_THREADS>>>(ei, W2, b2, out, E, M);
}

// round 8
// speedup vs baseline: 2.4216x; 1.0658x over previous
#include <cuda_runtime.h>
#include <cuda_bf16.h>
#include <cuda_fp16.h>
#include <cstdint>

#define HID   256
#define HID2  512
#define MAXN  50000

// Scratch
__device__ __half g_ABh[(size_t)MAXN * HID2];   // fp16 activations (b1 folded)
__device__ __nv_bfloat16 g_Wt_hi[HID2 * HID];   // [n][k], k-contiguous
__device__ __nv_bfloat16 g_Wt_lo[HID2 * HID];
__device__ __nv_bfloat16 g_Z_hi[(size_t)MAXN * HID];
__device__ __nv_bfloat16 g_Z_lo[(size_t)MAXN * HID];
__device__ int g_idx64_flag;

// ---------------------------------------------------------------------------
// helpers
// ---------------------------------------------------------------------------
__device__ __forceinline__ uint32_t smem_u32(const void* p) {
    uint32_t a;
    asm("{ .reg .u64 t; cvta.to.shared.u64 t, %1; cvt.u32.u64 %0, t; }"
        : "=r"(a) : "l"(p));
    return a;
}
__device__ __forceinline__ void cp16(uint32_t s, const void* g) {
    asm volatile("cp.async.cg.shared.global [%0], [%1], 16;" :: "r"(s), "l"(g) : "memory");
}
__device__ __forceinline__ void ldsm_x4(uint32_t* r, uint32_t a) {
    asm volatile("ldmatrix.sync.aligned.m8n8.x4.shared.b16 {%0,%1,%2,%3}, [%4];"
                 : "=r"(r[0]), "=r"(r[1]), "=r"(r[2]), "=r"(r[3]) : "r"(a));
}
__device__ __forceinline__ void ldsm_x2(uint32_t* r, uint32_t a) {
    asm volatile("ldmatrix.sync.aligned.m8n8.x2.shared.b16 {%0,%1}, [%2];"
                 : "=r"(r[0]), "=r"(r[1]) : "r"(a));
}
__device__ __forceinline__ void mma_bf16(float* c, const uint32_t* a, const uint32_t* b) {
    asm volatile("mma.sync.aligned.m16n8k16.row.col.f32.bf16.bf16.f32 "
                 "{%0,%1,%2,%3}, {%4,%5,%6,%7}, {%8,%9}, {%0,%1,%2,%3};"
                 : "+f"(c[0]), "+f"(c[1]), "+f"(c[2]), "+f"(c[3])
                 : "r"(a[0]), "r"(a[1]), "r"(a[2]), "r"(a[3]), "r"(b[0]), "r"(b[1]));
}
__device__ __forceinline__ uint32_t swz(int r, int kb) {
    return ((uint32_t)(r * 128 + kb)) ^ ((uint32_t)(r & 7) << 4);
}

// ---------------------------------------------------------------------------
// Probe edge_index dtype (int64 vs int32 on device)
// ---------------------------------------------------------------------------
__global__ void probe_kernel(const void* __restrict__ ei, int E, int N) {
    __shared__ int ok;
    if (threadIdx.x == 0) ok = 1;
    __syncthreads();
    const long long* p = (const long long*)ei;
    int total = 2 * E;
    int samples = total < 4096 ? total : 4096;
    for (int i = threadIdx.x; i < samples; i += blockDim.x) {
        long long v = p[i];
        if (v < 0 || v >= (long long)N) ok = 0;
    }
    __syncthreads();
    if (threadIdx.x == 0) g_idx64_flag = ok;
}

// ---------------------------------------------------------------------------
// Pack W1 [512,256] -> transposed split bf16 Wt_hi/Wt_lo [n=512][k=256]
// ---------------------------------------------------------------------------
__global__ void pack_w_kernel(const float* __restrict__ W1) {
    int idx = blockIdx.x * blockDim.x + threadIdx.x;
    if (idx >= HID2 * HID) return;
    int n = idx >> 8;
    int k = idx & (HID - 1);
    float v = (n < HID) ? W1[k * HID + n]
                        : W1[(HID + k) * HID + (n - HID)];
    __nv_bfloat16 hi = __float2bfloat16(v);
    float r = v - __bfloat162float(hi);
    g_Wt_hi[idx] = hi;
    g_Wt_lo[idx] = __float2bfloat16(r);
}

// ---------------------------------------------------------------------------
// Split z fp32 -> z_hi/z_lo bf16
// ---------------------------------------------------------------------------
__global__ void split_z_kernel(const float* __restrict__ z, int M) {
    int idx = blockIdx.x * blockDim.x + threadIdx.x;
    int total = M * HID / 8;
    if (idx >= total) return;
    const float4* p = reinterpret_cast<const float4*>(z) + (size_t)idx * 2;
    float4 v0 = p[0], v1 = p[1];
    float f[8] = {v0.x, v0.y, v0.z, v0.w, v1.x, v1.y, v1.z, v1.w};
    __nv_bfloat16 hi[8], lo[8];
#pragma unroll
    for (int i = 0; i < 8; i++) {
        hi[i] = __float2bfloat16(f[i]);
        lo[i] = __float2bfloat16(f[i] - __bfloat162float(hi[i]));
    }
    *reinterpret_cast<uint4*>(&g_Z_hi[(size_t)idx * 8]) = *reinterpret_cast<uint4*>(hi);
    *reinterpret_cast<uint4*>(&g_Z_lo[(size_t)idx * 8]) = *reinterpret_cast<uint4*>(lo);
}

// ---------------------------------------------------------------------------
// HMMA GEMM: AB[M,512] = z[M,256] @ W (+ b1 on cols>=256), fp16 output.
// bf16 split: D = Ahi*Bhi + Ahi*Blo + Alo*Bhi, fp32 accum.
// CTA tile 64m x 128n, 8 warps (2m x 4n, 32x32/warp), KC=64, 2-stage cp.async.
// 2 CTAs/SM (96KB smem, <=128 regs).
// ---------------------------------------------------------------------------
#define KC 64
#define OFF_AHI 0
#define OFF_ALO 8192
#define OFF_BHI 16384
#define OFF_BLO 32768
#define STAGE_BYTES 49152
#define SMEM_DYN (2 * STAGE_BYTES)   // 98304

__global__ __launch_bounds__(256, 2)
void hmma_kernel(const float* __restrict__ b1, int M) {
    extern __shared__ char smem[];
    uint32_t sb = smem_u32(smem);
    int tid = threadIdx.x;
    int wid = tid >> 5;
    int lane = tid & 31;
    int mBase = blockIdx.y * 64;
    int nBase = blockIdx.x * 128;
    int warpM = wid >> 2;     // 0..1 (32 rows each)
    int warpN = wid & 3;      // 0..3 (32 cols each)

    float c[2][4][4];
#pragma unroll
    for (int i = 0; i < 2; i++)
#pragma unroll
        for (int j = 0; j < 4; j++)
#pragma unroll
            for (int q = 0; q < 4; q++) c[i][j][q] = 0.f;

    // stage loader: A(64rows) hi/lo = 2x512 vec, B(128rows) hi/lo = 2x1024 vec
    auto load_stage = [&](int s, int kc) {
        uint32_t base = sb + s * STAGE_BYTES;
        int kOff = kc * KC;
        // B tiles: idx 0..1023
#pragma unroll
        for (int i = 0; i < 4; i++) {
            int idx = tid + i * 256;
            int r = idx >> 3;
            int kg = idx & 7;
            uint32_t sw = swz(r, kg * 16);
            size_t boff = (size_t)(nBase + r) * HID + kOff + kg * 8;
            cp16(base + OFF_BHI + sw, &g_Wt_hi[boff]);
            cp16(base + OFF_BLO + sw, &g_Wt_lo[boff]);
        }
        // A tiles: idx 0..511
#pragma unroll
        for (int i = 0; i < 2; i++) {
            int idx = tid + i * 256;
            int r = idx >> 3;
            int kg = idx & 7;
            uint32_t sw = swz(r, kg * 16);
            int ar = mBase + r;
            ar = ar < M ? ar : M - 1;
            size_t aoff = (size_t)ar * HID + kOff + kg * 8;
            cp16(base + OFF_AHI + sw, &g_Z_hi[aoff]);
            cp16(base + OFF_ALO + sw, &g_Z_lo[aoff]);
        }
        asm volatile("cp.async.commit_group;" ::: "memory");
    };

    load_stage(0, 0);
    load_stage(1, 1);

#pragma unroll 1
    for (int ck = 0; ck < 4; ck++) {
        if (ck < 3) asm volatile("cp.async.wait_group 1;" ::: "memory");
        else        asm volatile("cp.async.wait_group 0;" ::: "memory");
        __syncthreads();

        uint32_t base = sb + (ck & 1) * STAGE_BYTES;
#pragma unroll
        for (int ks = 0; ks < 4; ks++) {
            uint32_t ahi[2][4], alo[2][4], bhi[4][2], blo[4][2];
#pragma unroll
            for (int mf = 0; mf < 2; mf++) {
                int r = warpM * 32 + mf * 16 + (lane & 15);
                int kb = ks * 32 + ((lane >> 4) << 4);
                uint32_t sw = swz(r, kb);
                ldsm_x4(ahi[mf], base + OFF_AHI + sw);
                ldsm_x4(alo[mf], base + OFF_ALO + sw);
            }
#pragma unroll
            for (int nf = 0; nf < 4; nf++) {
                int l = lane & 15;
                int r = warpN * 32 + nf * 8 + (l & 7);
                int kb = ks * 32 + ((l >> 3) << 4);
                uint32_t sw = swz(r, kb);
                ldsm_x2(bhi[nf], base + OFF_BHI + sw);
                ldsm_x2(blo[nf], base + OFF_BLO + sw);
            }
#pragma unroll
            for (int mf = 0; mf < 2; mf++)
#pragma unroll
                for (int nf = 0; nf < 4; nf++) {
                    mma_bf16(c[mf][nf], ahi[mf], bhi[nf]);
                    mma_bf16(c[mf][nf], ahi[mf], blo[nf]);
                    mma_bf16(c[mf][nf], alo[mf], bhi[nf]);
                }
        }
        __syncthreads();
        if (ck + 2 < 4) load_stage(ck & 1, ck + 2);
    }

    // epilogue: +bias on cols>=256, convert to fp16, store half2
    int rowInFrag = lane >> 2;
    int colInFrag = (lane & 3) * 2;
#pragma unroll
    for (int nf = 0; nf < 4; nf++) {
        int col = nBase + warpN * 32 + nf * 8 + colInFrag;
        float bx = 0.f, by = 0.f;
        if (col >= HID) {
            bx = __ldg(&b1[col - HID]);
            by = __ldg(&b1[col - HID + 1]);
        }
#pragma unroll
        for (int mf = 0; mf < 2; mf++) {
            int row0 = mBase + warpM * 32 + mf * 16 + rowInFrag;
            if (row0 < M) {
                __half2 h = __floats2half2_rn(c[mf][nf][0] + bx, c[mf][nf][1] + by);
                *reinterpret_cast<__half2*>(&g_ABh[(size_t)row0 * HID2 + col]) = h;
            }
            int row1 = row0 + 8;
            if (row1 < M) {
                __half2 h = __floats2half2_rn(c[mf][nf][2] + bx, c[mf][nf][3] + by);
                *reinterpret_cast<__half2*>(&g_ABh[(size_t)row1 * HID2 + col]) = h;
            }
        }
    }
}

// ---------------------------------------------------------------------------
// Edge scores: fp16 AB gather (8 halves/lane/row), fp32 math.
// ---------------------------------------------------------------------------
#define EDGE_BLOCKS 1184
#define EDGE_THREADS 256

__global__ __launch_bounds__(EDGE_THREADS)
void edge_kernel(const void* __restrict__ ei_raw,
                 const float* __restrict__ W2,
                 const float* __restrict__ b2,
                 float* __restrict__ out,
                 int E, int M) {
    int lane = threadIdx.x & 31;
    int warp = (blockIdx.x * EDGE_THREADS + threadIdx.x) >> 5;
    int nwarps = (gridDim.x * EDGE_THREADS) >> 5;

    const float4* w2v = reinterpret_cast<const float4*>(W2);
    float4 wA = __ldg(&w2v[2 * lane]);
    float4 wB = __ldg(&w2v[2 * lane + 1]);
    float bias = __ldg(b2);

    int idx64 = g_idx64_flag;
    const long long* ei64 = (const long long*)ei_raw;
    const int*       ei32 = (const int*)ei_raw;

    for (int e = warp; e < E; e += nwarps) {
        long long s, d;
        if (idx64) {
            s = ei64[e];
            d = ei64[(size_t)E + e];
        } else {
            s = ei32[e];
            d = ei32[(size_t)E + e];
        }
        s = s < 0 ? 0 : (s >= M ? M - 1 : s);
        d = d < 0 ? 0 : (d >= M ? M - 1 : d);

        const uint4* Arow = reinterpret_cast<const uint4*>(g_ABh + (size_t)s * HID2);
        const uint4* Brow = reinterpret_cast<const uint4*>(g_ABh + (size_t)d * HID2 + HID);

        uint4 av = __ldg(&Arow[lane]);
        uint4 bv = __ldg(&Brow[lane]);
        const __half2* ah = reinterpret_cast<const __half2*>(&av);
        const __half2* bh = reinterpret_cast<const __half2*>(&bv);

        float2 a0 = __half22float2(ah[0]), b0 = __half22float2(bh[0]);
        float2 a1 = __half22float2(ah[1]), b1p = __half22float2(bh[1]);
        float2 a2 = __half22float2(ah[2]), b2p = __half22float2(bh[2]);
        float2 a3 = __half22float2(ah[3]), b3p = __half22float2(bh[3]);

        float acc = 0.f;
        acc = fmaf(fmaxf(a0.x + b0.x, 0.f), wA.x, acc);
        acc = fmaf(fmaxf(a0.y + b0.y, 0.f), wA.y, acc);
        acc = fmaf(fmaxf(a1.x + b1p.x, 0.f), wA.z, acc);
        acc = fmaf(fmaxf(a1.y + b1p.y, 0.f), wA.w, acc);
        acc = fmaf(fmaxf(a2.x + b2p.x, 0.f), wB.x, acc);
        acc = fmaf(fmaxf(a2.y + b2p.y, 0.f), wB.y, acc);
        acc = fmaf(fmaxf(a3.x + b3p.x, 0.f), wB.z, acc);
        acc = fmaf(fmaxf(a3.y + b3p.y, 0.f), wB.w, acc);

#pragma unroll
        for (int off = 16; off > 0; off >>= 1)
            acc += __shfl_xor_sync(0xFFFFFFFFu, acc, off);

        if (lane == 0)
            out[e] = acc + bias;
    }
}

// ---------------------------------------------------------------------------
// Launch
// ---------------------------------------------------------------------------
extern "C" void kernel_launch(void* const* d_in, const int* in_sizes, int n_in,
                              void* d_out, int out_size) {
    const float* z  = (const float*)d_in[0];
    const void*  ei = d_in[1];
    const float* W1 = (const float*)d_in[2];
    const float* b1 = (const float*)d_in[3];
    const float* W2 = (const float*)d_in[4];
    const float* b2 = (const float*)d_in[5];
    float* out = (float*)d_out;

    int M = in_sizes[0] / HID;   // nodes (50000)
    int E = in_sizes[1] / 2;     // edges (800000)

    probe_kernel<<<1, 256>>>(ei, E, M);
    pack_w_kernel<<<(HID2 * HID + 255) / 256, 256>>>(W1);
    split_z_kernel<<<(M * HID / 8 + 255) / 256, 256>>>(z, M);

    static int smem_set = 0;
    if (!smem_set) {
        cudaFuncSetAttribute(hmma_kernel,
                             cudaFuncAttributeMaxDynamicSharedMemorySize, SMEM_DYN);
        smem_set = 1;
    }
    dim3 grid(HID2 / 128, (M + 63) / 64);
    hmma_kernel<<<grid, 256, SMEM_DYN>>>(b1, M);

    edge_kernel<<<EDGE_BLOCKS, EDGE_THREADS>>>(ei, W2, b2, out, E, M);
}

// round 9
// speedup vs baseline: 2.6419x; 1.0910x over previous
#include <cuda_runtime.h>
#include <cuda_bf16.h>
#include <cuda_fp16.h>
#include <cstdint>

#define HID   256
#define HID2  512
#define MAXN  50000

// Scratch
__device__ __half g_ABh[(size_t)MAXN * HID2];   // fp16 activations (b1 folded)
__device__ __half g_Wt_hi[HID2 * HID];          // [n][k], k-contiguous, fp16 hi
__device__ __half g_Wt_lo[HID2 * HID];          // fp16 lo (subnormal range ok)
__device__ __half g_Z16[(size_t)MAXN * HID];    // z in fp16
__device__ int g_idx64_flag;

// ---------------------------------------------------------------------------
// helpers
// ---------------------------------------------------------------------------
__device__ __forceinline__ uint32_t smem_u32(const void* p) {
    uint32_t a;
    asm("{ .reg .u64 t; cvta.to.shared.u64 t, %1; cvt.u32.u64 %0, t; }"
        : "=r"(a) : "l"(p));
    return a;
}
__device__ __forceinline__ void cp16(uint32_t s, const void* g) {
    asm volatile("cp.async.cg.shared.global [%0], [%1], 16;" :: "r"(s), "l"(g) : "memory");
}
__device__ __forceinline__ void ldsm_x4(uint32_t* r, uint32_t a) {
    asm volatile("ldmatrix.sync.aligned.m8n8.x4.shared.b16 {%0,%1,%2,%3}, [%4];"
                 : "=r"(r[0]), "=r"(r[1]), "=r"(r[2]), "=r"(r[3]) : "r"(a));
}
__device__ __forceinline__ void ldsm_x2(uint32_t* r, uint32_t a) {
    asm volatile("ldmatrix.sync.aligned.m8n8.x2.shared.b16 {%0,%1}, [%2];"
                 : "=r"(r[0]), "=r"(r[1]) : "r"(a));
}
__device__ __forceinline__ void mma_f16(float* c, const uint32_t* a, const uint32_t* b) {
    asm volatile("mma.sync.aligned.m16n8k16.row.col.f32.f16.f16.f32 "
                 "{%0,%1,%2,%3}, {%4,%5,%6,%7}, {%8,%9}, {%0,%1,%2,%3};"
                 : "+f"(c[0]), "+f"(c[1]), "+f"(c[2]), "+f"(c[3])
                 : "r"(a[0]), "r"(a[1]), "r"(a[2]), "r"(a[3]), "r"(b[0]), "r"(b[1]));
}
__device__ __forceinline__ uint32_t swz(int r, int kb) {
    return ((uint32_t)(r * 128 + kb)) ^ ((uint32_t)(r & 7) << 4);
}

// ---------------------------------------------------------------------------
// Probe edge_index dtype (int64 vs int32 on device)
// ---------------------------------------------------------------------------
__global__ void probe_kernel(const void* __restrict__ ei, int E, int N) {
    __shared__ int ok;
    if (threadIdx.x == 0) ok = 1;
    __syncthreads();
    const long long* p = (const long long*)ei;
    int total = 2 * E;
    int samples = total < 4096 ? total : 4096;
    for (int i = threadIdx.x; i < samples; i += blockDim.x) {
        long long v = p[i];
        if (v < 0 || v >= (long long)N) ok = 0;
    }
    __syncthreads();
    if (threadIdx.x == 0) g_idx64_flag = ok;
}

// ---------------------------------------------------------------------------
// Pack W1 [512,256] -> transposed split fp16 Wt_hi/Wt_lo [n=512][k=256]
// ---------------------------------------------------------------------------
__global__ void pack_w_kernel(const float* __restrict__ W1) {
    int idx = blockIdx.x * blockDim.x + threadIdx.x;
    if (idx >= HID2 * HID) return;
    int n = idx >> 8;
    int k = idx & (HID - 1);
    float v = (n < HID) ? W1[k * HID + n]
                        : W1[(HID + k) * HID + (n - HID)];
    __half hi = __float2half_rn(v);
    float r = v - __half2float(hi);
    g_Wt_hi[idx] = hi;
    g_Wt_lo[idx] = __float2half_rn(r);
}

// ---------------------------------------------------------------------------
// Convert z fp32 -> fp16
// ---------------------------------------------------------------------------
__global__ void split_z_kernel(const float* __restrict__ z, int M) {
    int idx = blockIdx.x * blockDim.x + threadIdx.x;
    int total = M * HID / 8;
    if (idx >= total) return;
    const float4* p = reinterpret_cast<const float4*>(z) + (size_t)idx * 2;
    float4 v0 = p[0], v1 = p[1];
    __half h[8];
    h[0] = __float2half_rn(v0.x); h[1] = __float2half_rn(v0.y);
    h[2] = __float2half_rn(v0.z); h[3] = __float2half_rn(v0.w);
    h[4] = __float2half_rn(v1.x); h[5] = __float2half_rn(v1.y);
    h[6] = __float2half_rn(v1.z); h[7] = __float2half_rn(v1.w);
    *reinterpret_cast<uint4*>(&g_Z16[(size_t)idx * 8]) = *reinterpret_cast<uint4*>(h);
}

// ---------------------------------------------------------------------------
// HMMA GEMM: AB[M,512] = z[M,256] @ W (+ b1 on cols>=256), fp16 output.
// fp16 2-pass: D = A16*Whi + A16*Wlo, fp32 accum.
// CTA 64m x 128n, 8 warps (2m x 4n), KC=64, 2-stage cp.async, 2 CTAs/SM.
// ---------------------------------------------------------------------------
#define KC 64
#define OFF_A   0
#define OFF_BHI 8192
#define OFF_BLO 24576
#define STAGE_BYTES 40960
#define SMEM_DYN (2 * STAGE_BYTES)   // 81920

__global__ __launch_bounds__(256, 2)
void hmma_kernel(const float* __restrict__ b1, int M) {
    extern __shared__ char smem[];
    uint32_t sb = smem_u32(smem);
    int tid = threadIdx.x;
    int wid = tid >> 5;
    int lane = tid & 31;
    int mBase = blockIdx.y * 64;
    int nBase = blockIdx.x * 128;
    int warpM = wid >> 2;     // 0..1
    int warpN = wid & 3;      // 0..3

    float c[2][4][4];
#pragma unroll
    for (int i = 0; i < 2; i++)
#pragma unroll
        for (int j = 0; j < 4; j++)
#pragma unroll
            for (int q = 0; q < 4; q++) c[i][j][q] = 0.f;

    auto load_stage = [&](int s, int kc) {
        uint32_t base = sb + s * STAGE_BYTES;
        int kOff = kc * KC;
        // B hi/lo: 1024 vec16 each
#pragma unroll
        for (int i = 0; i < 4; i++) {
            int idx = tid + i * 256;
            int r = idx >> 3;
            int kg = idx & 7;
            uint32_t sw = swz(r, kg * 16);
            size_t boff = (size_t)(nBase + r) * HID + kOff + kg * 8;
            cp16(base + OFF_BHI + sw, &g_Wt_hi[boff]);
            cp16(base + OFF_BLO + sw, &g_Wt_lo[boff]);
        }
        // A: 512 vec16
        {
            int idx = tid;
            int r = idx >> 3;
            int kg = idx & 7;
            uint32_t sw = swz(r, kg * 16);
            int ar = mBase + r;
            ar = ar < M ? ar : M - 1;
            size_t aoff = (size_t)ar * HID + kOff + kg * 8;
            cp16(base + OFF_A + sw, &g_Z16[aoff]);
        }
        {
            int idx = tid + 256;
            int r = idx >> 3;
            int kg = idx & 7;
            uint32_t sw = swz(r, kg * 16);
            int ar = mBase + r;
            ar = ar < M ? ar : M - 1;
            size_t aoff = (size_t)ar * HID + kOff + kg * 8;
            cp16(base + OFF_A + sw, &g_Z16[aoff]);
        }
        asm volatile("cp.async.commit_group;" ::: "memory");
    };

    load_stage(0, 0);
    load_stage(1, 1);

#pragma unroll 1
    for (int ck = 0; ck < 4; ck++) {
        if (ck < 3) asm volatile("cp.async.wait_group 1;" ::: "memory");
        else        asm volatile("cp.async.wait_group 0;" ::: "memory");
        __syncthreads();

        uint32_t base = sb + (ck & 1) * STAGE_BYTES;
#pragma unroll
        for (int ks = 0; ks < 4; ks++) {
            uint32_t a16[2][4], bhi[4][2], blo[4][2];
#pragma unroll
            for (int mf = 0; mf < 2; mf++) {
                int r = warpM * 32 + mf * 16 + (lane & 15);
                int kb = ks * 32 + ((lane >> 4) << 4);
                ldsm_x4(a16[mf], base + OFF_A + swz(r, kb));
            }
#pragma unroll
            for (int nf = 0; nf < 4; nf++) {
                int l = lane & 15;
                int r = warpN * 32 + nf * 8 + (l & 7);
                int kb = ks * 32 + ((l >> 3) << 4);
                uint32_t sw = swz(r, kb);
                ldsm_x2(bhi[nf], base + OFF_BHI + sw);
                ldsm_x2(blo[nf], base + OFF_BLO + sw);
            }
#pragma unroll
            for (int mf = 0; mf < 2; mf++)
#pragma unroll
                for (int nf = 0; nf < 4; nf++) {
                    mma_f16(c[mf][nf], a16[mf], bhi[nf]);
                    mma_f16(c[mf][nf], a16[mf], blo[nf]);
                }
        }
        __syncthreads();
        if (ck + 2 < 4) load_stage(ck & 1, ck + 2);
    }

    // epilogue: +bias on cols>=256, convert to fp16, store half2
    int rowInFrag = lane >> 2;
    int colInFrag = (lane & 3) * 2;
#pragma unroll
    for (int nf = 0; nf < 4; nf++) {
        int col = nBase + warpN * 32 + nf * 8 + colInFrag;
        float bx = 0.f, by = 0.f;
        if (col >= HID) {
            bx = __ldg(&b1[col - HID]);
            by = __ldg(&b1[col - HID + 1]);
        }
#pragma unroll
        for (int mf = 0; mf < 2; mf++) {
            int row0 = mBase + warpM * 32 + mf * 16 + rowInFrag;
            if (row0 < M) {
                __half2 h = __floats2half2_rn(c[mf][nf][0] + bx, c[mf][nf][1] + by);
                *reinterpret_cast<__half2*>(&g_ABh[(size_t)row0 * HID2 + col]) = h;
            }
            int row1 = row0 + 8;
            if (row1 < M) {
                __half2 h = __floats2half2_rn(c[mf][nf][2] + bx, c[mf][nf][3] + by);
                *reinterpret_cast<__half2*>(&g_ABh[(size_t)row1 * HID2 + col]) = h;
            }
        }
    }
}

// ---------------------------------------------------------------------------
// Edge scores: fp16 AB gather (8 halves/lane/row), fp32 math.
// ---------------------------------------------------------------------------
#define EDGE_BLOCKS 1184
#define EDGE_THREADS 256

__global__ __launch_bounds__(EDGE_THREADS)
void edge_kernel(const void* __restrict__ ei_raw,
                 const float* __restrict__ W2,
                 const float* __restrict__ b2,
                 float* __restrict__ out,
                 int E, int M) {
    int lane = threadIdx.x & 31;
    int warp = (blockIdx.x * EDGE_THREADS + threadIdx.x) >> 5;
    int nwarps = (gridDim.x * EDGE_THREADS) >> 5;

    const float4* w2v = reinterpret_cast<const float4*>(W2);
    float4 wA = __ldg(&w2v[2 * lane]);
    float4 wB = __ldg(&w2v[2 * lane + 1]);
    float bias = __ldg(b2);

    int idx64 = g_idx64_flag;
    const long long* ei64 = (const long long*)ei_raw;
    const int*       ei32 = (const int*)ei_raw;

    for (int e = warp; e < E; e += nwarps) {
        long long s, d;
        if (idx64) {
            s = ei64[e];
            d = ei64[(size_t)E + e];
        } else {
            s = ei32[e];
            d = ei32[(size_t)E + e];
        }
        s = s < 0 ? 0 : (s >= M ? M - 1 : s);
        d = d < 0 ? 0 : (d >= M ? M - 1 : d);

        const uint4* Arow = reinterpret_cast<const uint4*>(g_ABh + (size_t)s * HID2);
        const uint4* Brow = reinterpret_cast<const uint4*>(g_ABh + (size_t)d * HID2 + HID);

        uint4 av = __ldg(&Arow[lane]);
        uint4 bv = __ldg(&Brow[lane]);
        const __half2* ah = reinterpret_cast<const __half2*>(&av);
        const __half2* bh = reinterpret_cast<const __half2*>(&bv);

        float2 a0 = __half22float2(ah[0]), b0 = __half22float2(bh[0]);
        float2 a1 = __half22float2(ah[1]), b1p = __half22float2(bh[1]);
        float2 a2 = __half22float2(ah[2]), b2p = __half22float2(bh[2]);
        float2 a3 = __half22float2(ah[3]), b3p = __half22float2(bh[3]);

        float acc = 0.f;
        acc = fmaf(fmaxf(a0.x + b0.x, 0.f), wA.x, acc);
        acc = fmaf(fmaxf(a0.y + b0.y, 0.f), wA.y, acc);
        acc = fmaf(fmaxf(a1.x + b1p.x, 0.f), wA.z, acc);
        acc = fmaf(fmaxf(a1.y + b1p.y, 0.f), wA.w, acc);
        acc = fmaf(fmaxf(a2.x + b2p.x, 0.f), wB.x, acc);
        acc = fmaf(fmaxf(a2.y + b2p.y, 0.f), wB.y, acc);
        acc = fmaf(fmaxf(a3.x + b3p.x, 0.f), wB.z, acc);
        acc = fmaf(fmaxf(a3.y + b3p.y, 0.f), wB.w, acc);

#pragma unroll
        for (int off = 16; off > 0; off >>= 1)
            acc += __shfl_xor_sync(0xFFFFFFFFu, acc, off);

        if (lane == 0)
            out[e] = acc + bias;
    }
}

// ---------------------------------------------------------------------------
// Launch
// ---------------------------------------------------------------------------
extern "C" void kernel_launch(void* const* d_in, const int* in_sizes, int n_in,
                              void* d_out, int out_size) {
    const float* z  = (const float*)d_in[0];
    const void*  ei = d_in[1];
    const float* W1 = (const float*)d_in[2];
    const float* b1 = (const float*)d_in[3];
    const float* W2 = (const float*)d_in[4];
    const float* b2 = (const float*)d_in[5];
    float* out = (float*)d_out;

    int M = in_sizes[0] / HID;   // nodes (50000)
    int E = in_sizes[1] / 2;     // edges (800000)

    probe_kernel<<<1, 256>>>(ei, E, M);
    pack_w_kernel<<<(HID2 * HID + 255) / 256, 256>>>(W1);
    split_z_kernel<<<(M * HID / 8 + 255) / 256, 256>>>(z, M);

    static int smem_set = 0;
    if (!smem_set) {
        cudaFuncSetAttribute(hmma_kernel,
                             cudaFuncAttributeMaxDynamicSharedMemorySize, SMEM_DYN);
        smem_set = 1;
    }
    dim3 grid(HID2 / 128, (M + 63) / 64);
    hmma_kernel<<<grid, 256, SMEM_DYN>>>(b1, M);

    edge_kernel<<<EDGE_BLOCKS, EDGE_THREADS>>>(ei, W2, b2, out, E, M);
}